// round 6
// baseline (speedup 1.0000x reference)
#include <cuda_runtime.h>
#include <cuda_fp16.h>
#include <cstdint>

// ---------------------------------------------------------------------------
// TFN forward. R6: revert enc to R4 shape (64x3 grid). Main kernel: prefetch
// distance 2 — chunk j LDG'd at iter j-2, cvt+STS'd at top of iter j-1 (no
// scoreboard wait), computed at iter j. Removes the per-chunk exposed LDG
// tail that made R4/R5 run ~2300 cyc/chunk vs ~1400 achievable.
// ---------------------------------------------------------------------------

#define NBLK   152
#define BDIM   64
#define HDIM   96
#define LDH    104            // smem B row stride in halfs (208 B, LDSM conflict-free)
#define KROWS  112            // 97 data rows + 15 zero pad (7 k16 steps)
#define WBUFH  (KROWS * LDH)  // halfs per buffer
#define SMEM_BYTES (2*WBUFH*2 + 2*6208*4)

__device__ float g_a1[BDIM * 97];
__device__ float g_v1[BDIM * 97];
__device__ float g_t1[BDIM * 97];
__device__ float g_part[NBLK * BDIM * HDIM];

// ---------------------------------------------------------------------------

__device__ __forceinline__ uint32_t h2u(__half2 h) {
    return *reinterpret_cast<uint32_t*>(&h);
}

__device__ __forceinline__ void mma_f16(float c[4],
                                        uint32_t a0, uint32_t a1,
                                        uint32_t a2, uint32_t a3,
                                        uint32_t b0, uint32_t b1) {
    asm volatile(
        "mma.sync.aligned.m16n8k16.row.col.f32.f16.f16.f32 "
        "{%0,%1,%2,%3}, {%4,%5,%6,%7}, {%8,%9}, {%0,%1,%2,%3};"
        : "+f"(c[0]), "+f"(c[1]), "+f"(c[2]), "+f"(c[3])
        : "r"(a0), "r"(a1), "r"(a2), "r"(a3), "r"(b0), "r"(b1));
}

struct __align__(8) H4 { __half2 a, b; };

// 97*96 = 9312 floats = 2328 float4 per chunk. 256 threads: 9 each + 24 extra.
__device__ __forceinline__ void stage_ldg(float4* stg,
                                          const float* __restrict__ W1,
                                          int av, int tid) {
    const float4* src = reinterpret_cast<const float4*>(W1 + (size_t)av * 9312);
#pragma unroll
    for (int j = 0; j < 9; j++) stg[j] = src[tid + j * 256];
    if (tid < 24) stg[9] = src[2304 + tid];
}

__device__ __forceinline__ void cvt_store(__half* buf, int q, float4 v) {
    int e = q * 4;
    int t = e / 96;
    int c = e - t * 96;
    H4 o;
    o.a = __floats2half2_rn(v.x, v.y);
    o.b = __floats2half2_rn(v.z, v.w);
    *reinterpret_cast<H4*>(buf + t * LDH + c) = o;
}

__device__ __forceinline__ void stage_sts(__half* buf, const float4* stg, int tid) {
#pragma unroll
    for (int j = 0; j < 9; j++) cvt_store(buf, tid + j * 256, stg[j]);
    if (tid < 24) cvt_store(buf, 2304 + tid, stg[9]);
}

// ---------------------------------------------------------------------------
// Kernel 1: encoders. grid (64 batch, 3 mods), 768 threads = 96 h x 8 slices.
// ---------------------------------------------------------------------------
__global__ void __launch_bounds__(768) tfn_enc(
    const float* __restrict__ audios, const float* __restrict__ texts,
    const float* __restrict__ videos,
    const float* __restrict__ Wa, const float* __restrict__ ba,
    const float* __restrict__ Wt, const float* __restrict__ bt,
    const float* __restrict__ Wv, const float* __restrict__ bv) {
    const int b   = blockIdx.x;
    const int mod = blockIdx.y;
    const int tid = threadIdx.x;

    const float* x; const float* W; const float* bias; float* out; int K;
    if (mod == 0)      { x = audios; W = Wa; bias = ba; out = g_a1; K = 512; }
    else if (mod == 1) { x = texts;  W = Wt; bias = bt; out = g_t1; K = 1024; }
    else               { x = videos; W = Wv; bias = bv; out = g_v1; K = 512; }

    __shared__ float xs[1024];
    __shared__ float ps[768];

    const float* xb = x + (size_t)b * K;
    for (int i = tid; i < K; i += 768) xs[i] = xb[i];
    __syncthreads();

    const int h  = tid % 96;
    const int g  = tid / 96;           // 0..7
    const int kq = K >> 3;             // 64 or 128
    const int k0 = g * kq;

    float acc = 0.f;
#pragma unroll 8
    for (int k = k0; k < k0 + kq; k++)
        acc += xs[k] * W[k * HDIM + h];
    ps[tid] = acc;
    __syncthreads();

    if (g == 0) {
        float r = bias[h];
#pragma unroll
        for (int i = 0; i < 8; i++) r += ps[h + 96 * i];
        out[b * 97 + 1 + h] = fmaxf(r, 0.f);
        if (h == 0) out[b * 97] = 1.f;
    }
}

// ---------------------------------------------------------------------------
// Kernel 2: main fused trilinear GEMM (y1 partials, pre-bias/relu)
//   grid = 152 CTAs x 256 threads, 1 CTA/SM, prefetch distance 2
// ---------------------------------------------------------------------------
__global__ void __launch_bounds__(256, 1) tfn_main(const float* __restrict__ W1) {
    extern __shared__ char smx[];
    __half* wb0 = reinterpret_cast<__half*>(smx);
    __half* wb1 = wb0 + WBUFH;
    float*  a1s = reinterpret_cast<float*>(wb1 + WBUFH);
    float*  v1s = a1s + 6208;

    const int tid  = threadIdx.x;
    const int lane = tid & 31;
    const int wid  = tid >> 5;
    const int wm   = wid & 3;    // m-warp: batch rows 16*wm..16*wm+15
    const int wn   = wid >> 2;   // n-warp: cols 48*wn..48*wn+47
    const int gid  = lane >> 2;
    const int tig  = lane & 3;
    const int b0   = wm * 16 + gid;
    const int nbase = wn * 48;

    for (int i = tid; i < 6208; i += 256) { a1s[i] = g_a1[i]; v1s[i] = g_v1[i]; }
    // zero pad rows 97..111 of both buffers (k-tail; A frags there are 0 too)
    {
        uint32_t* z0 = reinterpret_cast<uint32_t*>(wb0 + 97 * LDH);
        uint32_t* z1 = reinterpret_cast<uint32_t*>(wb1 + 97 * LDH);
        for (int i = tid; i < (15 * LDH) / 2; i += 256) { z0[i] = 0; z1[i] = 0; }
    }

    // persistent t1 A-fragments as half2 pairs: 7 k16-steps
    __half2 t1f[7][4];
#pragma unroll
    for (int ks = 0; ks < 7; ks++) {
        int ka = ks * 16 + 2 * tig;
        int kb = ka + 8;
        float x0 = (ka     < 97) ? g_t1[b0 * 97 + ka]           : 0.f;
        float x1 = (ka + 1 < 97) ? g_t1[b0 * 97 + ka + 1]       : 0.f;
        float y0 = (ka     < 97) ? g_t1[(b0 + 8) * 97 + ka]     : 0.f;
        float y1 = (ka + 1 < 97) ? g_t1[(b0 + 8) * 97 + ka + 1] : 0.f;
        float x2 = (kb     < 97) ? g_t1[b0 * 97 + kb]           : 0.f;
        float x3 = (kb + 1 < 97) ? g_t1[b0 * 97 + kb + 1]       : 0.f;
        float y2 = (kb     < 97) ? g_t1[(b0 + 8) * 97 + kb]     : 0.f;
        float y3 = (kb + 1 < 97) ? g_t1[(b0 + 8) * 97 + kb + 1] : 0.f;
        t1f[ks][0] = __floats2half2_rn(x0, x1);
        t1f[ks][1] = __floats2half2_rn(y0, y1);
        t1f[ks][2] = __floats2half2_rn(x2, x3);
        t1f[ks][3] = __floats2half2_rn(y2, y3);
    }

    float Y[6][4];
#pragma unroll
    for (int j = 0; j < 6; j++) { Y[j][0] = Y[j][1] = Y[j][2] = Y[j][3] = 0.f; }

    const int bk = blockIdx.x;
    // 9409 = 152*61 + 137 : first 137 blocks take 62 chunks
    const int cstart = (bk < 137) ? bk * 62 : bk * 61 + 137;
    const int ccnt   = (bk < 137) ? 62 : 61;

    // per-thread LDSM row components
    const int lrow = lane & 15;          // k row within k16 step
    const int lcol = (lane >> 4) * 8;    // 0 or 8 within n16 block

    // --- prefetch distance 2: chunk j in stg[j&1]; LDG at j-2, STS at j-1 ---
    float4 stg[2][10];
    stage_ldg(stg[0], W1, cstart, tid);
    if (ccnt > 1) stage_ldg(stg[1], W1, cstart + 1, tid);
    stage_sts(wb0, stg[0], tid);
    __syncthreads();

    for (int ci = 0; ci < ccnt; ci++) {
        const __half* cur = (ci & 1) ? wb1 : wb0;
        __half* nxt       = (ci & 1) ? wb0 : wb1;
        const int av = cstart + ci;

        // STS chunk ci+1 (its LDG completed ~1 chunk-time ago: no stall),
        // then kick off LDG for chunk ci+2 into the freed register slot.
        if (ci + 1 < ccnt) stage_sts(nxt, stg[(ci + 1) & 1], tid);
        if (ci + 2 < ccnt) stage_ldg(stg[ci & 1], W1, av + 2, tid);

        const int ca = av / 97;
        const int cv = av - ca * 97;
        const __half2 m0h = __float2half2_rn(a1s[b0 * 97 + ca] * v1s[b0 * 97 + cv]);
        const __half2 m1h = __float2half2_rn(a1s[(b0 + 8) * 97 + ca] * v1s[(b0 + 8) * 97 + cv]);

#pragma unroll
        for (int ks = 0; ks < 7; ks++) {
            const uint32_t A0 = h2u(__hmul2(m0h, t1f[ks][0]));
            const uint32_t A1 = h2u(__hmul2(m1h, t1f[ks][1]));
            const uint32_t A2 = h2u(__hmul2(m0h, t1f[ks][2]));
            const uint32_t A3 = h2u(__hmul2(m1h, t1f[ks][3]));
            const __half* rowp = cur + (ks * 16 + lrow) * LDH + nbase + lcol;
#pragma unroll
            for (int j3 = 0; j3 < 3; j3++) {
                uint32_t saddr =
                    (uint32_t)__cvta_generic_to_shared(rowp + 16 * j3);
                uint32_t B0, B1, B2, B3;
                asm volatile(
                    "ldmatrix.sync.aligned.m8n8.x4.trans.shared.b16 "
                    "{%0,%1,%2,%3}, [%4];"
                    : "=r"(B0), "=r"(B1), "=r"(B2), "=r"(B3) : "r"(saddr));
                mma_f16(Y[2 * j3],     A0, A1, A2, A3, B0, B1);
                mma_f16(Y[2 * j3 + 1], A0, A1, A2, A3, B2, B3);
            }
        }

        __syncthreads();
    }

    // write fp32 partials [bk][b][h]
    float* dst = g_part + (size_t)bk * (BDIM * HDIM);
#pragma unroll
    for (int j = 0; j < 6; j++) {
        int h = nbase + 8 * j + 2 * tig;
        *reinterpret_cast<float2*>(dst + b0 * HDIM + h) =
            make_float2(Y[j][0], Y[j][1]);
        *reinterpret_cast<float2*>(dst + (b0 + 8) * HDIM + h) =
            make_float2(Y[j][2], Y[j][3]);
    }
}

// ---------------------------------------------------------------------------
// Kernel 3: reduce partials + bias/relu + W2 + heads. One block per batch row.
// ---------------------------------------------------------------------------
__global__ void __launch_bounds__(768) tfn_tail(
    const float* __restrict__ b1, const float* __restrict__ W2,
    const float* __restrict__ b2,
    const float* __restrict__ Wo1, const float* __restrict__ bo1,
    const float* __restrict__ Wo2, const float* __restrict__ bo2,
    const float* __restrict__ Wo3, const float* __restrict__ bo3,
    float* __restrict__ out) {
    __shared__ float ps[768];
    __shared__ float yr[HDIM];
    __shared__ float fs[HDIM];
    const int b   = blockIdx.x;
    const int tid = threadIdx.x;
    const int h   = tid % 96;
    const int g   = tid / 96;   // 0..7

    float acc = 0.f;
#pragma unroll 4
    for (int p = g; p < NBLK; p += 8)
        acc += g_part[(size_t)p * (BDIM * HDIM) + b * HDIM + h];
    ps[tid] = acc;
    __syncthreads();

    if (g == 0) {
        float r = b1[h];
#pragma unroll
        for (int i = 0; i < 8; i++) r += ps[h + 96 * i];
        yr[h] = fmaxf(r, 0.f);
    }
    __syncthreads();

    if (g == 0) {
        float f = b2[h];
#pragma unroll 8
        for (int k = 0; k < HDIM; k++) f += yr[k] * W2[k * HDIM + h];
        f = fmaxf(f, 0.f);
        fs[h] = f;
        out[b * HDIM + h] = f;
    }
    __syncthreads();

    if (tid < 6) {
        float a = bo1[tid];
        for (int k = 0; k < HDIM; k++) a += fs[k] * Wo1[k * 6 + tid];
        out[6144 + b * 6 + tid] = a;
    } else if (tid == 6) {
        float a = bo2[0];
        for (int k = 0; k < HDIM; k++) a += fs[k] * Wo2[k];
        out[6528 + b] = a;
    } else if (tid < 10) {
        int o = tid - 7;
        float a = bo3[o];
        for (int k = 0; k < HDIM; k++) a += fs[k] * Wo3[k * 3 + o];
        out[6592 + b * 3 + o] = a;
    }
    if (b == 0 && tid == 95) out[6784] = 0.f;  // interloss
}

// ---------------------------------------------------------------------------

extern "C" void kernel_launch(void* const* d_in, const int* in_sizes, int n_in,
                              void* d_out, int out_size) {
    (void)in_sizes; (void)n_in; (void)out_size;
    const float* audios = (const float*)d_in[0];
    const float* texts  = (const float*)d_in[1];
    const float* videos = (const float*)d_in[2];
    const float* Wa  = (const float*)d_in[3];
    const float* ba  = (const float*)d_in[4];
    const float* Wt  = (const float*)d_in[5];
    const float* bt  = (const float*)d_in[6];
    const float* Wv  = (const float*)d_in[7];
    const float* bv  = (const float*)d_in[8];
    const float* W1  = (const float*)d_in[9];
    const float* b1  = (const float*)d_in[10];
    const float* W2  = (const float*)d_in[11];
    const float* b2  = (const float*)d_in[12];
    const float* Wo1 = (const float*)d_in[13];
    const float* bo1 = (const float*)d_in[14];
    const float* Wo2 = (const float*)d_in[15];
    const float* bo2 = (const float*)d_in[16];
    const float* Wo3 = (const float*)d_in[17];
    const float* bo3 = (const float*)d_in[18];
    float* out = (float*)d_out;

    cudaFuncSetAttribute(tfn_main, cudaFuncAttributeMaxDynamicSharedMemorySize,
                         SMEM_BYTES);

    tfn_enc<<<dim3(64, 3), 768>>>(audios, texts, videos, Wa, ba, Wt, bt, Wv, bv);
    tfn_main<<<NBLK, 256, SMEM_BYTES>>>(W1);
    tfn_tail<<<64, 768>>>(b1, W2, b2, Wo1, bo1, Wo2, bo2, Wo3, bo3, out);
}

// round 7
// speedup vs baseline: 1.5273x; 1.5273x over previous
#include <cuda_runtime.h>
#include <cuda_fp16.h>
#include <cstdint>

// ---------------------------------------------------------------------------
// TFN forward. R7: prefetch-distance-2 pipeline redone with STATIC staging
// buffers (explicit unroll-by-2; R6's dynamic-indexed stg[2][10] spilled to
// local memory and regressed to 150us). Even iters: STS stgB, LDG->stgA.
// Odd iters: STS stgA, LDG->stgB. enc/tail = R4-proven versions.
// ---------------------------------------------------------------------------

#define NBLK   152
#define BDIM   64
#define HDIM   96
#define LDH    104            // smem B row stride in halfs (208 B, LDSM conflict-free)
#define KROWS  112            // 97 data rows + 15 zero pad (7 k16 steps)
#define WBUFH  (KROWS * LDH)  // halfs per buffer
#define SMEM_BYTES (2*WBUFH*2 + 2*6208*4)

__device__ float g_a1[BDIM * 97];
__device__ float g_v1[BDIM * 97];
__device__ float g_t1[BDIM * 97];
__device__ float g_part[NBLK * BDIM * HDIM];

// ---------------------------------------------------------------------------

__device__ __forceinline__ uint32_t h2u(__half2 h) {
    return *reinterpret_cast<uint32_t*>(&h);
}

__device__ __forceinline__ void mma_f16(float c[4],
                                        uint32_t a0, uint32_t a1,
                                        uint32_t a2, uint32_t a3,
                                        uint32_t b0, uint32_t b1) {
    asm volatile(
        "mma.sync.aligned.m16n8k16.row.col.f32.f16.f16.f32 "
        "{%0,%1,%2,%3}, {%4,%5,%6,%7}, {%8,%9}, {%0,%1,%2,%3};"
        : "+f"(c[0]), "+f"(c[1]), "+f"(c[2]), "+f"(c[3])
        : "r"(a0), "r"(a1), "r"(a2), "r"(a3), "r"(b0), "r"(b1));
}

struct __align__(8) H4 { __half2 a, b; };

// 97*96 = 9312 floats = 2328 float4 per chunk. 256 threads: 9 each + 24 extra.
__device__ __forceinline__ void stage_ldg(float4 (&stg)[10],
                                          const float* __restrict__ W1,
                                          int av, int tid) {
    const float4* src = reinterpret_cast<const float4*>(W1 + (size_t)av * 9312);
#pragma unroll
    for (int j = 0; j < 9; j++) stg[j] = src[tid + j * 256];
    if (tid < 24) stg[9] = src[2304 + tid];
}

__device__ __forceinline__ void cvt_store(__half* buf, int q, float4 v) {
    int e = q * 4;
    int t = e / 96;
    int c = e - t * 96;
    H4 o;
    o.a = __floats2half2_rn(v.x, v.y);
    o.b = __floats2half2_rn(v.z, v.w);
    *reinterpret_cast<H4*>(buf + t * LDH + c) = o;
}

__device__ __forceinline__ void stage_sts(__half* buf, const float4 (&stg)[10],
                                          int tid) {
#pragma unroll
    for (int j = 0; j < 9; j++) cvt_store(buf, tid + j * 256, stg[j]);
    if (tid < 24) cvt_store(buf, 2304 + tid, stg[9]);
}

// ---------------------------------------------------------------------------
// Kernel 1: encoders. grid (64 batch, 3 mods), 768 threads = 96 h x 8 slices.
// ---------------------------------------------------------------------------
__global__ void __launch_bounds__(768) tfn_enc(
    const float* __restrict__ audios, const float* __restrict__ texts,
    const float* __restrict__ videos,
    const float* __restrict__ Wa, const float* __restrict__ ba,
    const float* __restrict__ Wt, const float* __restrict__ bt,
    const float* __restrict__ Wv, const float* __restrict__ bv) {
    const int b   = blockIdx.x;
    const int mod = blockIdx.y;
    const int tid = threadIdx.x;

    const float* x; const float* W; const float* bias; float* out; int K;
    if (mod == 0)      { x = audios; W = Wa; bias = ba; out = g_a1; K = 512; }
    else if (mod == 1) { x = texts;  W = Wt; bias = bt; out = g_t1; K = 1024; }
    else               { x = videos; W = Wv; bias = bv; out = g_v1; K = 512; }

    __shared__ float xs[1024];
    __shared__ float ps[768];

    const float* xb = x + (size_t)b * K;
    for (int i = tid; i < K; i += 768) xs[i] = xb[i];
    __syncthreads();

    const int h  = tid % 96;
    const int g  = tid / 96;           // 0..7
    const int kq = K >> 3;             // 64 or 128
    const int k0 = g * kq;

    float acc = 0.f;
#pragma unroll 8
    for (int k = k0; k < k0 + kq; k++)
        acc += xs[k] * W[k * HDIM + h];
    ps[tid] = acc;
    __syncthreads();

    if (g == 0) {
        float r = bias[h];
#pragma unroll
        for (int i = 0; i < 8; i++) r += ps[h + 96 * i];
        out[b * 97 + 1 + h] = fmaxf(r, 0.f);
        if (h == 0) out[b * 97] = 1.f;
    }
}

// ---------------------------------------------------------------------------
// Kernel 2: main fused trilinear GEMM (y1 partials, pre-bias/relu)
//   grid = 152 CTAs x 256 threads, 1 CTA/SM, prefetch distance 2 (static regs)
// ---------------------------------------------------------------------------
__global__ void __launch_bounds__(256, 1) tfn_main(const float* __restrict__ W1) {
    extern __shared__ char smx[];
    __half* wb0 = reinterpret_cast<__half*>(smx);
    __half* wb1 = wb0 + WBUFH;
    float*  a1s = reinterpret_cast<float*>(wb1 + WBUFH);
    float*  v1s = a1s + 6208;

    const int tid  = threadIdx.x;
    const int lane = tid & 31;
    const int wid  = tid >> 5;
    const int wm   = wid & 3;    // m-warp: batch rows 16*wm..16*wm+15
    const int wn   = wid >> 2;   // n-warp: cols 48*wn..48*wn+47
    const int gid  = lane >> 2;
    const int tig  = lane & 3;
    const int b0   = wm * 16 + gid;
    const int nbase = wn * 48;

    for (int i = tid; i < 6208; i += 256) { a1s[i] = g_a1[i]; v1s[i] = g_v1[i]; }
    // zero pad rows 97..111 of both buffers (k-tail; A frags there are 0 too)
    {
        uint32_t* z0 = reinterpret_cast<uint32_t*>(wb0 + 97 * LDH);
        uint32_t* z1 = reinterpret_cast<uint32_t*>(wb1 + 97 * LDH);
        for (int i = tid; i < (15 * LDH) / 2; i += 256) { z0[i] = 0; z1[i] = 0; }
    }

    // persistent t1 A-fragments as half2 pairs: 7 k16-steps
    __half2 t1f[7][4];
#pragma unroll
    for (int ks = 0; ks < 7; ks++) {
        int ka = ks * 16 + 2 * tig;
        int kb = ka + 8;
        float x0 = (ka     < 97) ? g_t1[b0 * 97 + ka]           : 0.f;
        float x1 = (ka + 1 < 97) ? g_t1[b0 * 97 + ka + 1]       : 0.f;
        float y0 = (ka     < 97) ? g_t1[(b0 + 8) * 97 + ka]     : 0.f;
        float y1 = (ka + 1 < 97) ? g_t1[(b0 + 8) * 97 + ka + 1] : 0.f;
        float x2 = (kb     < 97) ? g_t1[b0 * 97 + kb]           : 0.f;
        float x3 = (kb + 1 < 97) ? g_t1[b0 * 97 + kb + 1]       : 0.f;
        float y2 = (kb     < 97) ? g_t1[(b0 + 8) * 97 + kb]     : 0.f;
        float y3 = (kb + 1 < 97) ? g_t1[(b0 + 8) * 97 + kb + 1] : 0.f;
        t1f[ks][0] = __floats2half2_rn(x0, x1);
        t1f[ks][1] = __floats2half2_rn(y0, y1);
        t1f[ks][2] = __floats2half2_rn(x2, x3);
        t1f[ks][3] = __floats2half2_rn(y2, y3);
    }

    float Y[6][4];
#pragma unroll
    for (int j = 0; j < 6; j++) { Y[j][0] = Y[j][1] = Y[j][2] = Y[j][3] = 0.f; }

    const int bk = blockIdx.x;
    // 9409 = 152*61 + 137 : first 137 blocks take 62 chunks
    const int cstart = (bk < 137) ? bk * 62 : bk * 61 + 137;
    const int ccnt   = (bk < 137) ? 62 : 61;

    // per-thread LDSM row components
    const int lrow = lane & 15;          // k row within k16 step
    const int lcol = (lane >> 4) * 8;    // 0 or 8 within n16 block

    // compute body: MMA over one chunk resident in `cur`
    auto compute = [&](int av, const __half* cur) {
        const int ca = av / 97;
        const int cv = av - ca * 97;
        const __half2 m0h = __float2half2_rn(a1s[b0 * 97 + ca] * v1s[b0 * 97 + cv]);
        const __half2 m1h = __float2half2_rn(a1s[(b0 + 8) * 97 + ca] * v1s[(b0 + 8) * 97 + cv]);
#pragma unroll
        for (int ks = 0; ks < 7; ks++) {
            const uint32_t A0 = h2u(__hmul2(m0h, t1f[ks][0]));
            const uint32_t A1 = h2u(__hmul2(m1h, t1f[ks][1]));
            const uint32_t A2 = h2u(__hmul2(m0h, t1f[ks][2]));
            const uint32_t A3 = h2u(__hmul2(m1h, t1f[ks][3]));
            const __half* rowp = cur + (ks * 16 + lrow) * LDH + nbase + lcol;
#pragma unroll
            for (int j3 = 0; j3 < 3; j3++) {
                uint32_t saddr =
                    (uint32_t)__cvta_generic_to_shared(rowp + 16 * j3);
                uint32_t B0, B1, B2, B3;
                asm volatile(
                    "ldmatrix.sync.aligned.m8n8.x4.trans.shared.b16 "
                    "{%0,%1,%2,%3}, [%4];"
                    : "=r"(B0), "=r"(B1), "=r"(B2), "=r"(B3) : "r"(saddr));
                mma_f16(Y[2 * j3],     A0, A1, A2, A3, B0, B1);
                mma_f16(Y[2 * j3 + 1], A0, A1, A2, A3, B2, B3);
            }
        }
    };

    // --- prefetch distance 2, statically named buffers ---
    float4 stgA[10], stgB[10];
    stage_ldg(stgA, W1, cstart, tid);
    if (ccnt > 1) stage_ldg(stgB, W1, cstart + 1, tid);
    stage_sts(wb0, stgA, tid);
    __syncthreads();

    for (int ci = 0; ci < ccnt; ci += 2) {
        // even iteration: compute chunk ci from wb0
        if (ci + 1 < ccnt) stage_sts(wb1, stgB, tid);           // chunk ci+1
        if (ci + 2 < ccnt) stage_ldg(stgA, W1, cstart + ci + 2, tid);
        compute(cstart + ci, wb0);
        __syncthreads();

        // odd iteration: compute chunk ci+1 from wb1
        if (ci + 1 < ccnt) {
            if (ci + 2 < ccnt) stage_sts(wb0, stgA, tid);       // chunk ci+2
            if (ci + 3 < ccnt) stage_ldg(stgB, W1, cstart + ci + 3, tid);
            compute(cstart + ci + 1, wb1);
            __syncthreads();
        }
    }

    // write fp32 partials [bk][b][h]
    float* dst = g_part + (size_t)bk * (BDIM * HDIM);
#pragma unroll
    for (int j = 0; j < 6; j++) {
        int h = nbase + 8 * j + 2 * tig;
        *reinterpret_cast<float2*>(dst + b0 * HDIM + h) =
            make_float2(Y[j][0], Y[j][1]);
        *reinterpret_cast<float2*>(dst + (b0 + 8) * HDIM + h) =
            make_float2(Y[j][2], Y[j][3]);
    }
}

// ---------------------------------------------------------------------------
// Kernel 3: reduce partials + bias/relu + W2 + heads. One block per batch row.
// ---------------------------------------------------------------------------
__global__ void __launch_bounds__(768) tfn_tail(
    const float* __restrict__ b1, const float* __restrict__ W2,
    const float* __restrict__ b2,
    const float* __restrict__ Wo1, const float* __restrict__ bo1,
    const float* __restrict__ Wo2, const float* __restrict__ bo2,
    const float* __restrict__ Wo3, const float* __restrict__ bo3,
    float* __restrict__ out) {
    __shared__ float ps[768];
    __shared__ float yr[HDIM];
    __shared__ float fs[HDIM];
    const int b   = blockIdx.x;
    const int tid = threadIdx.x;
    const int h   = tid % 96;
    const int g   = tid / 96;   // 0..7

    float acc = 0.f;
#pragma unroll 4
    for (int p = g; p < NBLK; p += 8)
        acc += g_part[(size_t)p * (BDIM * HDIM) + b * HDIM + h];
    ps[tid] = acc;
    __syncthreads();

    if (g == 0) {
        float r = b1[h];
#pragma unroll
        for (int i = 0; i < 8; i++) r += ps[h + 96 * i];
        yr[h] = fmaxf(r, 0.f);
    }
    __syncthreads();

    if (g == 0) {
        float f = b2[h];
#pragma unroll 8
        for (int k = 0; k < HDIM; k++) f += yr[k] * W2[k * HDIM + h];
        f = fmaxf(f, 0.f);
        fs[h] = f;
        out[b * HDIM + h] = f;
    }
    __syncthreads();

    if (tid < 6) {
        float a = bo1[tid];
        for (int k = 0; k < HDIM; k++) a += fs[k] * Wo1[k * 6 + tid];
        out[6144 + b * 6 + tid] = a;
    } else if (tid == 6) {
        float a = bo2[0];
        for (int k = 0; k < HDIM; k++) a += fs[k] * Wo2[k];
        out[6528 + b] = a;
    } else if (tid < 10) {
        int o = tid - 7;
        float a = bo3[o];
        for (int k = 0; k < HDIM; k++) a += fs[k] * Wo3[k * 3 + o];
        out[6592 + b * 3 + o] = a;
    }
    if (b == 0 && tid == 95) out[6784] = 0.f;  // interloss
}

// ---------------------------------------------------------------------------

extern "C" void kernel_launch(void* const* d_in, const int* in_sizes, int n_in,
                              void* d_out, int out_size) {
    (void)in_sizes; (void)n_in; (void)out_size;
    const float* audios = (const float*)d_in[0];
    const float* texts  = (const float*)d_in[1];
    const float* videos = (const float*)d_in[2];
    const float* Wa  = (const float*)d_in[3];
    const float* ba  = (const float*)d_in[4];
    const float* Wt  = (const float*)d_in[5];
    const float* bt  = (const float*)d_in[6];
    const float* Wv  = (const float*)d_in[7];
    const float* bv  = (const float*)d_in[8];
    const float* W1  = (const float*)d_in[9];
    const float* b1  = (const float*)d_in[10];
    const float* W2  = (const float*)d_in[11];
    const float* b2  = (const float*)d_in[12];
    const float* Wo1 = (const float*)d_in[13];
    const float* bo1 = (const float*)d_in[14];
    const float* Wo2 = (const float*)d_in[15];
    const float* bo2 = (const float*)d_in[16];
    const float* Wo3 = (const float*)d_in[17];
    const float* bo3 = (const float*)d_in[18];
    float* out = (float*)d_out;

    cudaFuncSetAttribute(tfn_main, cudaFuncAttributeMaxDynamicSharedMemorySize,
                         SMEM_BYTES);

    tfn_enc<<<dim3(64, 3), 768>>>(audios, texts, videos, Wa, ba, Wt, bt, Wv, bv);
    tfn_main<<<NBLK, 256, SMEM_BYTES>>>(W1);
    tfn_tail<<<64, 768>>>(b1, W2, b2, Wo1, bo1, Wo2, bo2, Wo3, bo3, out);
}